// round 15
// baseline (speedup 1.0000x reference)
#include <cuda_runtime.h>
#include <cuda_bf16.h>
#include <math.h>
#include <stdint.h>

#define S_ 256
#define D_ 256
#define B_ 1024
#define LOG2PI 1.8378770664093453f

// Scratch (no runtime allocation allowed)
__device__ float g_M[S_ * D_ * D_];    // Gram -> overwritten in place by L (lower)
__device__ float g_LT[S_ * D_ * D_];   // L transposed (k-major), lower part valid
__device__ float g_W[S_ * D_ * D_];    // W = L^{-1} fp32 (used inside cholinv)
__device__ float g_logdet[S_];
// bf16 hi/lo split arrays. Phase 1: transposed sp ([s][d][k]) for gram.
// Phase 2 (after gram consumed them): W split ([s][row][col]) for maha.
__device__ __nv_bfloat16 g_bfH[S_ * D_ * D_];
__device__ __nv_bfloat16 g_bfL[S_ * D_ * D_];

// ---------------------------------------------------------------------------
// helpers
// ---------------------------------------------------------------------------
__device__ __forceinline__ uint32_t smem_u32(const void* p) {
    uint32_t a;
    asm("{ .reg .u64 t; cvta.to.shared.u64 t, %1; cvt.u32.u64 %0, t; }"
        : "=r"(a) : "l"(p));
    return a;
}
#define LDSM_X4(r, addr) \
    asm volatile("ldmatrix.sync.aligned.m8n8.x4.shared.b16 {%0,%1,%2,%3}, [%4];" \
                 : "=r"((r)[0]), "=r"((r)[1]), "=r"((r)[2]), "=r"((r)[3]) \
                 : "r"(addr))
#define LDSM_X2(r, addr) \
    asm volatile("ldmatrix.sync.aligned.m8n8.x2.shared.b16 {%0,%1}, [%2];" \
                 : "=r"((r)[0]), "=r"((r)[1]) : "r"(addr))
#define MMA16816(c, a, b) \
    asm volatile("mma.sync.aligned.m16n8k16.row.col.f32.bf16.bf16.f32 " \
                 "{%0,%1,%2,%3}, {%4,%5,%6,%7}, {%8,%9}, {%0,%1,%2,%3};" \
                 : "+f"((c)[0]), "+f"((c)[1]), "+f"((c)[2]), "+f"((c)[3]) \
                 : "r"((a)[0]), "r"((a)[1]), "r"((a)[2]), "r"((a)[3]), \
                   "r"((b)[0]), "r"((b)[1]))
#define CP_ASYNC16(dst, src) \
    asm volatile("cp.async.cg.shared.global [%0], [%1], 16;" \
                 :: "r"(dst), "l"(src) : "memory")
#define CP_COMMIT() asm volatile("cp.async.commit_group;" ::: "memory")
#define CP_WAIT0()  asm volatile("cp.async.wait_group 0;" ::: "memory")

__device__ __forceinline__ uint32_t pack_split(float f0, float f1, uint32_t& lo) {
    __nv_bfloat16 h0 = __float2bfloat16(f0);
    __nv_bfloat16 h1 = __float2bfloat16(f1);
    __nv_bfloat16 l0 = __float2bfloat16(f0 - __bfloat162float(h0));
    __nv_bfloat16 l1 = __float2bfloat16(f1 - __bfloat162float(h1));
    __nv_bfloat162 hp = __halves2bfloat162(h0, h1);
    __nv_bfloat162 lp = __halves2bfloat162(l0, l1);
    lo = *(uint32_t*)&lp;
    return *(uint32_t*)&hp;
}
__device__ __forceinline__ void split8(float4 a, float4 b, uint4& h, uint4& l) {
    h.x = pack_split(a.x, a.y, l.x);
    h.y = pack_split(a.z, a.w, l.y);
    h.z = pack_split(b.x, b.y, l.z);
    h.w = pack_split(b.z, b.w, l.w);
}

// ---------------------------------------------------------------------------
// Kernel 0: tsplit — sp (fp32 [s][k][d]) -> g_bfH/g_bfL (bf16, TRANSPOSED [s][d][k])
// ---------------------------------------------------------------------------
__global__ __launch_bounds__(256) void tsplit_kernel(const float* __restrict__ sp) {
    __shared__ unsigned short H[64][72];
    __shared__ unsigned short L[64][72];
    const int s = blockIdx.y;
    const int k0 = (blockIdx.x >> 2) * 64;
    const int d0 = (blockIdx.x & 3) * 64;
    const int t = threadIdx.x;
    const int r16 = t >> 4, c4 = (t & 15) * 4;

#pragma unroll
    for (int rr = 0; rr < 4; ++rr) {
        int kr = rr * 16 + r16;
        float4 v = *(const float4*)&sp[s * 65536 + (k0 + kr) * 256 + d0 + c4];
        uint32_t l01, l23;
        uint32_t h01 = pack_split(v.x, v.y, l01);
        uint32_t h23 = pack_split(v.z, v.w, l23);
        *(uint32_t*)&H[kr][c4]     = h01;
        *(uint32_t*)&H[kr][c4 + 2] = h23;
        *(uint32_t*)&L[kr][c4]     = l01;
        *(uint32_t*)&L[kr][c4 + 2] = l23;
    }
    __syncthreads();

    const int dr = t >> 2, q = t & 3;
#pragma unroll
    for (int h = 0; h < 2; ++h) {
        int kc = q * 16 + h * 8;
        uint32_t wh[4], wl[4];
#pragma unroll
        for (int j = 0; j < 4; ++j) {
            wh[j] = (uint32_t)H[kc + 2 * j][dr] | ((uint32_t)H[kc + 2 * j + 1][dr] << 16);
            wl[j] = (uint32_t)L[kc + 2 * j][dr] | ((uint32_t)L[kc + 2 * j + 1][dr] << 16);
        }
        int gi = s * 65536 + (d0 + dr) * 256 + k0 + kc;
        *(uint4*)&g_bfH[gi] = make_uint4(wh[0], wh[1], wh[2], wh[3]);
        *(uint4*)&g_bfL[gi] = make_uint4(wl[0], wl[1], wl[2], wl[3]);
    }
}

// ---------------------------------------------------------------------------
// Kernel 1: Gram via HMMA bf16 split. M[s] = Sp^T Sp, tiles (0,0),(1,0),(1,1).
// ---------------------------------------------------------------------------
#define ASTRIDE 72
#define ABUF (128 * ASTRIDE)
#define GEMM_SMEM (4 * ABUF * 2)

__global__ __launch_bounds__(256) void gram_mma_kernel() {
    extern __shared__ char shm[];
    __nv_bfloat16* AH = (__nv_bfloat16*)shm;
    __nv_bfloat16* AL = AH + ABUF;
    __nv_bfloat16* BH = AL + ABUF;
    __nv_bfloat16* BL = BH + ABUF;

    const int t = blockIdx.x;            // 0:(0,0) 1:(1,0) 2:(1,1)
    const int s = blockIdx.y;
    const int di = (t == 0) ? 0 : 1;
    const int ei = (t == 2) ? 1 : 0;
    const int tid = threadIdx.x;
    const int wid = tid >> 5, lane = tid & 31;
    const int wr = wid >> 2, wc = wid & 3;

    float c[4][4][4];
#pragma unroll
    for (int mt = 0; mt < 4; ++mt)
#pragma unroll
        for (int nt = 0; nt < 4; ++nt)
#pragma unroll
            for (int q = 0; q < 4; ++q) c[mt][nt][q] = 0.f;

    const int rowq = tid >> 1, half = tid & 1;
    const int sb = s * 65536;

    for (int ch = 0; ch < 4; ++ch) {
        const int k0 = ch * 64;
        __syncthreads();
#pragma unroll
        for (int j = 0; j < 4; ++j) {
            int kc = half * 32 + j * 8;
            int ga = sb + (di * 128 + rowq) * 256 + k0 + kc;
            int gb = sb + (ei * 128 + rowq) * 256 + k0 + kc;
            *(uint4*)(AH + rowq * ASTRIDE + kc) = *(const uint4*)&g_bfH[ga];
            *(uint4*)(AL + rowq * ASTRIDE + kc) = *(const uint4*)&g_bfL[ga];
            *(uint4*)(BH + rowq * ASTRIDE + kc) = *(const uint4*)&g_bfH[gb];
            *(uint4*)(BL + rowq * ASTRIDE + kc) = *(const uint4*)&g_bfL[gb];
        }
        __syncthreads();

        const int ar = lane & 15, as8 = (lane >> 4) * 8;
        const int br = lane & 7,  bs8 = ((lane >> 3) & 1) * 8;
#pragma unroll
        for (int ks = 0; ks < 4; ++ks) {
            const int kk = ks * 16;
            uint32_t aH[4][4], aL[4][4], bH[4][2], bL[4][2];
#pragma unroll
            for (int mt = 0; mt < 4; ++mt) {
                int row = wr * 64 + mt * 16 + ar;
                LDSM_X4(aH[mt], smem_u32(AH + row * ASTRIDE + kk + as8));
                LDSM_X4(aL[mt], smem_u32(AL + row * ASTRIDE + kk + as8));
            }
#pragma unroll
            for (int nt = 0; nt < 4; ++nt) {
                int row = wc * 32 + nt * 8 + br;
                LDSM_X2(bH[nt], smem_u32(BH + row * ASTRIDE + kk + bs8));
                LDSM_X2(bL[nt], smem_u32(BL + row * ASTRIDE + kk + bs8));
            }
#pragma unroll
            for (int mt = 0; mt < 4; ++mt)
#pragma unroll
                for (int nt = 0; nt < 4; ++nt) {
                    MMA16816(c[mt][nt], aH[mt], bH[nt]);
                    MMA16816(c[mt][nt], aH[mt], bL[nt]);
                    MMA16816(c[mt][nt], aL[mt], bH[nt]);
                }
        }
    }

    float* Cg = g_M + sb;
#pragma unroll
    for (int mt = 0; mt < 4; ++mt)
#pragma unroll
        for (int nt = 0; nt < 4; ++nt) {
            int r0 = di * 128 + wr * 64 + mt * 16 + (lane >> 2);
            int cc = ei * 128 + wc * 32 + nt * 8 + (lane & 3) * 2;
            *(float2*)&Cg[r0 * 256 + cc]       = make_float2(c[mt][nt][0], c[mt][nt][1]);
            *(float2*)&Cg[(r0 + 8) * 256 + cc] = make_float2(c[mt][nt][2], c[mt][nt][3]);
        }
}

// ---------------------------------------------------------------------------
// Kernel 2: blocked Cholesky + logdet + blocked inversion (identical to R14).
// ---------------------------------------------------------------------------
#define PPAD 68
#define P_FLOATS (256 * PPAD)
#define STG_FLOATS (64 * PPAD)
#define CHOL_SMEM_FLOATS (P_FLOATS + 2 * STG_FLOATS + 256)

__global__ __launch_bounds__(256) void cholinv_kernel() {
    extern __shared__ float sh[];
    float* P   = sh;
    float* As  = sh + P_FLOATS;
    float* Bs  = sh + P_FLOATS + STG_FLOATS;
    float* red = sh + P_FLOATS + 2 * STG_FLOATS;

    const int s = blockIdx.x;
    const int tid = threadIdx.x;
    const int sb = s * 65536;
    const float* Ms = g_M + sb;
    float* Mw = g_M + sb;
    float* LT = g_LT + sb;
    float* Wg = g_W + sb;

    const int rg = (tid >> 4) * 4;
    const int cg = (tid & 15) * 4;

    red[tid] = Ms[tid * D_ + tid];
    __syncthreads();
    for (int o = 128; o > 0; o >>= 1) {
        if (tid < o) red[tid] += red[tid + o];
        __syncthreads();
    }
    const float ridge = 0.01f * red[0] / (float)D_;
    __syncthreads();

    for (int J = 0; J < 4; ++J) {
        const int R = 256 - 64 * J;
        const int g0 = 64 * J;

        for (int e = tid; e < R * 16; e += 256) {
            int pr = e >> 4, c4 = (e & 15) * 4;
            float4 v = *(const float4*)&Ms[(g0 + pr) * D_ + g0 + c4];
            *(float4*)&P[pr * PPAD + c4] = v;
        }
        __syncthreads();
        if (tid < 64) P[tid * PPAD + tid] += ridge;
        __syncthreads();

        for (int K = 0; K < J; ++K) {
            __syncthreads();
            for (int e = tid; e < 1024; e += 256) {
                int k = e >> 4, c4 = (e & 15) * 4;
                float4 v = *(const float4*)&LT[(64 * K + k) * D_ + g0 + c4];
                *(float4*)&Bs[k * PPAD + c4] = v;
            }
            for (int I = J; I < 4; ++I) {
                __syncthreads();
                for (int e = tid; e < 1024; e += 256) {
                    int k = e >> 4, r4 = (e & 15) * 4;
                    float4 v = *(const float4*)&LT[(64 * K + k) * D_ + 64 * I + r4];
                    *(float4*)&As[k * PPAD + r4] = v;
                }
                __syncthreads();
                float acc[4][4];
#pragma unroll
                for (int r = 0; r < 4; ++r)
#pragma unroll
                    for (int c = 0; c < 4; ++c) acc[r][c] = 0.f;
#pragma unroll 4
                for (int kk = 0; kk < 64; ++kk) {
                    float4 a = *(const float4*)&As[kk * PPAD + rg];
                    float4 b = *(const float4*)&Bs[kk * PPAD + cg];
                    float av[4] = {a.x, a.y, a.z, a.w};
                    float bv[4] = {b.x, b.y, b.z, b.w};
#pragma unroll
                    for (int r = 0; r < 4; ++r)
#pragma unroll
                        for (int c = 0; c < 4; ++c) acc[r][c] += av[r] * bv[c];
                }
                const int prb = 64 * (I - J);
#pragma unroll
                for (int r = 0; r < 4; ++r)
#pragma unroll
                    for (int c = 0; c < 4; ++c)
                        P[(prb + rg + r) * PPAD + cg + c] -= acc[r][c];
            }
        }
        __syncthreads();

        for (int jj = 0; jj < 64; ++jj) {
            const int pr = jj + tid;
            const bool act = pr < R;
            float num = 0.f;
            if (act) {
                const float* rp = P + pr * PPAD;
                const float* rj = P + jj * PPAD;
                float a0 = 0.f, a1 = 0.f, a2 = 0.f, a3 = 0.f;
                const int j4 = jj & ~3;
                for (int k = 0; k < j4; k += 4) {
                    float4 u = *(const float4*)(rp + k);
                    float4 v = *(const float4*)(rj + k);
                    a0 += u.x * v.x; a1 += u.y * v.y;
                    a2 += u.z * v.z; a3 += u.w * v.w;
                }
                for (int k = j4; k < jj; ++k) a0 += rp[k] * rj[k];
                num = rp[jj] - ((a0 + a1) + (a2 + a3));
            }
            if (tid == 0) red[0] = num;
            __syncthreads();
            const float dj = sqrtf(red[0]);
            if (act) P[pr * PPAD + jj] = (tid == 0) ? dj : num / dj;
            __syncthreads();
        }

        for (int e = tid; e < R * 16; e += 256) {
            int pr = e >> 4, c4 = (e & 15) * 4;
            float4 v = *(const float4*)&P[pr * PPAD + c4];
            *(float4*)&Mw[(g0 + pr) * D_ + g0 + c4] = v;
        }
        for (int c = 0; c < 64; ++c) {
            for (int pr = tid; pr < R; pr += 256)
                LT[(g0 + c) * D_ + g0 + pr] = P[pr * PPAD + c];
        }
        __syncthreads();
    }

    red[tid] = 2.f * logf(Mw[tid * D_ + tid]);
    __syncthreads();
    for (int o = 128; o > 0; o >>= 1) {
        if (tid < o) red[tid] += red[tid + o];
        __syncthreads();
    }
    if (tid == 0) g_logdet[s] = red[0];
    __syncthreads();

    for (int t = tid; t < 16384; t += 256) P[t] = 0.f;
    __syncthreads();

    for (int rnd = 0; rnd < 2; ++rnd) {
        for (int e = tid; e < 1024; e += 256) {
            int ii = e >> 4, t4 = (e & 15) * 4;
            int K0 = 2 * rnd, K1 = 2 * rnd + 1;
            *(float4*)&As[ii * 64 + t4] =
                *(const float4*)&Mw[(64 * K0 + ii) * D_ + 64 * K0 + t4];
            *(float4*)&Bs[ii * 64 + t4] =
                *(const float4*)&Mw[(64 * K1 + ii) * D_ + 64 * K1 + t4];
        }
        __syncthreads();
        if (tid < 128) {
            const int g = tid >> 6;
            const int jj = tid & 63;
            const int K = 2 * rnd + g;
            float* WK = P + K * 4096;
            const float* Ld = g ? Bs : As;
            for (int ii = jj; ii < 64; ++ii) {
                float acc = (ii == jj) ? 1.f : 0.f;
                for (int t = jj; t < ii; ++t) acc -= Ld[ii * 64 + t] * WK[t * 64 + jj];
                WK[ii * 64 + jj] = acc / Ld[ii * 64 + ii];
            }
        }
        __syncthreads();
    }

    for (int e = tid; e < 8192; e += 256) {
        int Kb = e >> 11, rr = (e >> 5) & 63, c2 = (e & 31) * 2;
        float v0 = P[Kb * 4096 + rr * 64 + c2];
        float v1 = P[Kb * 4096 + rr * 64 + c2 + 1];
        int gi = (64 * Kb + rr) * D_ + 64 * Kb + c2;
        Wg[gi] = v0; Wg[gi + 1] = v1;
        uint32_t lo, hi = pack_split(v0, v1, lo);
        *(uint32_t*)&g_bfH[sb + gi] = hi;
        *(uint32_t*)&g_bfL[sb + gi] = lo;
    }
    for (int e = tid; e < 6 * 2048; e += 256) {
        int bb = e >> 11, rr = (e >> 5) & 63, c2 = (e & 31) * 2;
        int I = (bb < 3) ? 0 : ((bb < 5) ? 1 : 2);
        int J = (bb < 3) ? (bb + 1) : ((bb == 3) ? 2 : 3);
        int gi = (64 * I + rr) * D_ + 64 * J + c2;
        Wg[gi] = 0.f; Wg[gi + 1] = 0.f;
        *(uint32_t*)&g_bfH[sb + gi] = 0u;
        *(uint32_t*)&g_bfL[sb + gi] = 0u;
    }
    __syncthreads();

    for (int J = 0; J < 3; ++J) {
        for (int I = J + 1; I < 4; ++I) {
            float acc[4][4];
#pragma unroll
            for (int r = 0; r < 4; ++r)
#pragma unroll
                for (int c = 0; c < 4; ++c) acc[r][c] = 0.f;

            for (int K = J; K < I; ++K) {
                __syncthreads();
                for (int e = tid; e < 1024; e += 256) {
                    int k = e >> 4, r4 = (e & 15) * 4;
                    float4 v = *(const float4*)&LT[(64 * K + k) * D_ + 64 * I + r4];
                    *(float4*)&As[k * PPAD + r4] = v;
                }
                for (int e = tid; e < 1024; e += 256) {
                    int k = e >> 4, c4 = (e & 15) * 4;
                    float4 v;
                    if (K == J) {
                        v = make_float4(P[J * 4096 + k * 64 + c4 + 0],
                                        P[J * 4096 + k * 64 + c4 + 1],
                                        P[J * 4096 + k * 64 + c4 + 2],
                                        P[J * 4096 + k * 64 + c4 + 3]);
                    } else {
                        v = *(const float4*)&Wg[(64 * K + k) * D_ + 64 * J + c4];
                    }
                    *(float4*)&Bs[k * PPAD + c4] = v;
                }
                __syncthreads();
#pragma unroll 4
                for (int kk = 0; kk < 64; ++kk) {
                    float4 a = *(const float4*)&As[kk * PPAD + rg];
                    float4 b = *(const float4*)&Bs[kk * PPAD + cg];
                    float av[4] = {a.x, a.y, a.z, a.w};
                    float bv[4] = {b.x, b.y, b.z, b.w};
#pragma unroll
                    for (int r = 0; r < 4; ++r)
#pragma unroll
                        for (int c = 0; c < 4; ++c) acc[r][c] += av[r] * bv[c];
                }
            }
            __syncthreads();
#pragma unroll
            for (int r = 0; r < 4; ++r)
#pragma unroll
                for (int c = 0; c < 4; ++c)
                    Bs[(rg + r) * PPAD + cg + c] = acc[r][c];
            __syncthreads();
            float o[4][4];
#pragma unroll
            for (int r = 0; r < 4; ++r)
#pragma unroll
                for (int c = 0; c < 4; ++c) o[r][c] = 0.f;
            const float* wA = P + I * 4096;
#pragma unroll 4
            for (int kk = 0; kk < 64; ++kk) {
                float av[4];
#pragma unroll
                for (int r = 0; r < 4; ++r) av[r] = wA[(rg + r) * 64 + kk];
                float4 b = *(const float4*)&Bs[kk * PPAD + cg];
                float bv[4] = {b.x, b.y, b.z, b.w};
#pragma unroll
                for (int r = 0; r < 4; ++r)
#pragma unroll
                    for (int c = 0; c < 4; ++c) o[r][c] += av[r] * bv[c];
            }
#pragma unroll
            for (int r = 0; r < 4; ++r) {
                float n0 = -o[r][0], n1 = -o[r][1], n2 = -o[r][2], n3 = -o[r][3];
                int gi = (64 * I + rg + r) * D_ + 64 * J + cg;
                *(float4*)&Wg[gi] = make_float4(n0, n1, n2, n3);
                uint32_t l01, l23;
                uint32_t h01 = pack_split(n0, n1, l01);
                uint32_t h23 = pack_split(n2, n3, l23);
                *(uint2*)&g_bfH[sb + gi] = make_uint2(h01, h23);
                *(uint2*)&g_bfL[sb + gi] = make_uint2(l01, l23);
            }
        }
    }
}

// ---------------------------------------------------------------------------
// Kernel 3: maha — cp.async double-buffered pipelined HMMA.
// Flattened 6-chunk list: ci 0-1 (dt=0, k0=0,64), ci 2-5 (dt=1, k0=0..192).
// While MMAs consume buf[cur], cp.async fills A(next) + raw x(next)->Bf32;
// B subtract-split runs post-MMA from smem. Epilogue after ci==1 and ci==5.
// ---------------------------------------------------------------------------
#define BF32STRIDE 68
#define MAHA_SMEM (2 * 4 * ABUF * 2 + 128 * BF32STRIDE * 4 + 256 * 4 + 256 * 4)

__global__ __launch_bounds__(256) void maha_mma_kernel(const float* __restrict__ x,
                                                       const float* __restrict__ mu,
                                                       float* __restrict__ out) {
    extern __shared__ char shm[];
    __nv_bfloat16* bufs = (__nv_bfloat16*)shm;   // [2][4][ABUF]
    float* Bf   = (float*)(shm + 2 * 4 * ABUF * 2);          // 128 x 68 fp32
    float* mu_s = Bf + 128 * BF32STRIDE;                     // 256
    float* sacc = mu_s + 256;                                // 256

    const int s = blockIdx.y;
    const int b0 = blockIdx.x * 128;
    const int tid = threadIdx.x;
    const int wid = tid >> 5, lane = tid & 31;
    const int wr = wid >> 2;
    const int wc = wid & 3;

    sacc[tid] = 0.f;
    mu_s[tid] = mu[s * 256 + tid];

    const int sb = s * 65536;
    const int rowq = tid >> 1, half = tid & 1;   // A staging
    const int srow = tid >> 3, sk8 = (tid & 7) * 8;  // B staging / split

    // chunk table: ci -> (dt, k0)
    auto chunk_dt = [](int ci) { return (ci >= 2) ? 1 : 0; };
    auto chunk_k0 = [](int ci) { return ((ci >= 2) ? (ci - 2) : ci) * 64; };

    // stage A(ci) into buffer b via cp.async; stage raw x(ci) into Bf
    auto stageA = [&](int ci, int b) {
        const int dt = chunk_dt(ci), k0 = chunk_k0(ci);
        __nv_bfloat16* AH = bufs + (size_t)b * 4 * ABUF;
        __nv_bfloat16* AL = AH + ABUF;
#pragma unroll
        for (int j = 0; j < 4; ++j) {
            int kc = half * 32 + j * 8;
            const __nv_bfloat16* gh = &g_bfH[sb + (dt * 128 + rowq) * 256 + k0 + kc];
            const __nv_bfloat16* gl = &g_bfL[sb + (dt * 128 + rowq) * 256 + k0 + kc];
            CP_ASYNC16(smem_u32(AH + rowq * ASTRIDE + kc), gh);
            CP_ASYNC16(smem_u32(AL + rowq * ASTRIDE + kc), gl);
        }
    };
    auto stageBraw = [&](int ci) {
        const int k0 = chunk_k0(ci);
#pragma unroll
        for (int it = 0; it < 4; ++it) {
            int row = srow + it * 32;
            const float* src = x + (size_t)(b0 + row) * 256 + k0 + sk8;
            uint32_t dst = smem_u32(Bf + row * BF32STRIDE + sk8);
            CP_ASYNC16(dst, src);
            CP_ASYNC16(dst + 16, src + 4);
        }
    };
    // split Bf (raw x) minus mu into BH/BL of buffer b for chunk ci
    auto splitB = [&](int ci, int b) {
        const int k0 = chunk_k0(ci);
        __nv_bfloat16* BH = bufs + (size_t)b * 4 * ABUF + 2 * ABUF;
        __nv_bfloat16* BL = BH + ABUF;
        float m0 = mu_s[k0 + sk8 + 0], m1 = mu_s[k0 + sk8 + 1];
        float m2 = mu_s[k0 + sk8 + 2], m3 = mu_s[k0 + sk8 + 3];
        float m4 = mu_s[k0 + sk8 + 4], m5 = mu_s[k0 + sk8 + 5];
        float m6 = mu_s[k0 + sk8 + 6], m7 = mu_s[k0 + sk8 + 7];
#pragma unroll
        for (int it = 0; it < 4; ++it) {
            int row = srow + it * 32;
            float4 u = *(const float4*)&Bf[row * BF32STRIDE + sk8];
            float4 v = *(const float4*)&Bf[row * BF32STRIDE + sk8 + 4];
            u.x -= m0; u.y -= m1; u.z -= m2; u.w -= m3;
            v.x -= m4; v.y -= m5; v.z -= m6; v.w -= m7;
            uint4 hq, lq; split8(u, v, hq, lq);
            *(uint4*)(BH + row * ASTRIDE + sk8) = hq;
            *(uint4*)(BL + row * ASTRIDE + sk8) = lq;
        }
    };

    // ---- prologue: stage chunk 0 ----
    stageA(0, 0);
    stageBraw(0);
    CP_COMMIT();
    CP_WAIT0();
    __syncthreads();
    splitB(0, 0);
    __syncthreads();

    float c[4][4][4];
    const int ar = lane & 15, as8 = (lane >> 4) * 8;
    const int br = lane & 7,  bs8 = ((lane >> 3) & 1) * 8;

    int cur = 0;
#pragma unroll 1
    for (int ci = 0; ci < 6; ++ci) {
        if (ci == 0 || ci == 2) {
#pragma unroll
            for (int mt = 0; mt < 4; ++mt)
#pragma unroll
                for (int nt = 0; nt < 4; ++nt)
#pragma unroll
                    for (int q = 0; q < 4; ++q) c[mt][nt][q] = 0.f;
        }

        // issue staging for next chunk (overlaps with MMAs below)
        if (ci + 1 < 6) {
            stageA(ci + 1, 1 - cur);
            stageBraw(ci + 1);
            CP_COMMIT();
        }

        // ---- MMAs on buf[cur] ----
        {
            __nv_bfloat16* AH = bufs + (size_t)cur * 4 * ABUF;
            __nv_bfloat16* AL = AH + ABUF;
            __nv_bfloat16* BH = AL + ABUF;
            __nv_bfloat16* BL = BH + ABUF;
#pragma unroll
            for (int ks = 0; ks < 4; ++ks) {
                const int kk = ks * 16;
                uint32_t bH[4][2], bL[4][2];
#pragma unroll
                for (int nt = 0; nt < 4; ++nt) {
                    int row = wc * 32 + nt * 8 + br;
                    LDSM_X2(bH[nt], smem_u32(BH + row * ASTRIDE + kk + bs8));
                    LDSM_X2(bL[nt], smem_u32(BL + row * ASTRIDE + kk + bs8));
                }
#pragma unroll
                for (int mt = 0; mt < 4; ++mt) {
                    int row = wr * 64 + mt * 16 + ar;
                    uint32_t aH[4], aL[4];
                    LDSM_X4(aH, smem_u32(AH + row * ASTRIDE + kk + as8));
                    LDSM_X4(aL, smem_u32(AL + row * ASTRIDE + kk + as8));
#pragma unroll
                    for (int nt = 0; nt < 4; ++nt) {
                        MMA16816(c[mt][nt], aH, bH[nt]);
                        MMA16816(c[mt][nt], aH, bL[nt]);
                        MMA16816(c[mt][nt], aL, bH[nt]);
                    }
                }
            }
        }

        // ---- epilogue at end of each d-tile ----
        if (ci == 1 || ci == 5) {
#pragma unroll
            for (int nt = 0; nt < 4; ++nt) {
                float p0 = 0.f, p1 = 0.f;
#pragma unroll
                for (int mt = 0; mt < 4; ++mt) {
                    p0 += c[mt][nt][0] * c[mt][nt][0] + c[mt][nt][2] * c[mt][nt][2];
                    p1 += c[mt][nt][1] * c[mt][nt][1] + c[mt][nt][3] * c[mt][nt][3];
                }
#pragma unroll
                for (int m = 4; m <= 16; m <<= 1) {
                    p0 += __shfl_xor_sync(0xffffffffu, p0, m);
                    p1 += __shfl_xor_sync(0xffffffffu, p1, m);
                }
                if (lane < 4) {
                    int col = wc * 32 + nt * 8 + 2 * lane;
                    sacc[wr * 128 + col]     += p0;
                    sacc[wr * 128 + col + 1] += p1;
                }
            }
        }

        // ---- finish staging of next chunk, split B ----
        if (ci + 1 < 6) {
            CP_WAIT0();
            __syncthreads();      // MMAs done reading buf[cur]; Bf arrived
            splitB(ci + 1, 1 - cur);
            __syncthreads();      // BH/BL[next] visible to all warps
            cur ^= 1;
        }
    }

    __syncthreads();
    if (tid < 128) {
        float m = sacc[tid] + sacc[128 + tid];
        out[(b0 + tid) * S_ + s] = -0.5f * ((float)D_ * LOG2PI + g_logdet[s] + m);
    }
}

// ---------------------------------------------------------------------------
extern "C" void kernel_launch(void* const* d_in, const int* in_sizes, int n_in,
                              void* d_out, int out_size) {
    const float* x  = (const float*)d_in[0];   // (B, D)
    const float* mu = (const float*)d_in[1];   // (S, 1, D)
    const float* sp = (const float*)d_in[2];   // (S, 1, D, D)
    float* out = (float*)d_out;                // (B, S)

    const int chol_smem = CHOL_SMEM_FLOATS * sizeof(float);   // 105,472 B
    cudaFuncSetAttribute(cholinv_kernel,
                         cudaFuncAttributeMaxDynamicSharedMemorySize, chol_smem);
    cudaFuncSetAttribute(gram_mma_kernel,
                         cudaFuncAttributeMaxDynamicSharedMemorySize, GEMM_SMEM);
    cudaFuncSetAttribute(maha_mma_kernel,
                         cudaFuncAttributeMaxDynamicSharedMemorySize, MAHA_SMEM);

    tsplit_kernel<<<dim3(16, S_), 256>>>(sp);
    gram_mma_kernel<<<dim3(3, S_), 256, GEMM_SMEM>>>();
    cholinv_kernel<<<S_, 256, chol_smem>>>();
    maha_mma_kernel<<<dim3(B_ / 128, S_), 256, MAHA_SMEM>>>(x, mu, out);
}

// round 16
// speedup vs baseline: 1.7392x; 1.7392x over previous
#include <cuda_runtime.h>
#include <cuda_bf16.h>
#include <math.h>
#include <stdint.h>

#define S_ 256
#define D_ 256
#define B_ 1024
#define LOG2PI 1.8378770664093453f

// Scratch (no runtime allocation allowed)
__device__ float g_M[S_ * D_ * D_];    // Gram -> overwritten in place by L (lower)
__device__ float g_LT[S_ * D_ * D_];   // L transposed (k-major), lower part valid
__device__ float g_W[S_ * D_ * D_];    // W = L^{-1} fp32 (used inside cholinv)
__device__ float g_logdet[S_];
// bf16 hi/lo split arrays. Phase 1: transposed sp ([s][d][k]) for gram.
// Phase 2 (after gram consumed them): W split ([s][row][col]) for maha.
__device__ __nv_bfloat16 g_bfH[S_ * D_ * D_];
__device__ __nv_bfloat16 g_bfL[S_ * D_ * D_];

// ---------------------------------------------------------------------------
// helpers
// ---------------------------------------------------------------------------
__device__ __forceinline__ uint32_t smem_u32(const void* p) {
    uint32_t a;
    asm("{ .reg .u64 t; cvta.to.shared.u64 t, %1; cvt.u32.u64 %0, t; }"
        : "=r"(a) : "l"(p));
    return a;
}
#define LDSM_X4(r, addr) \
    asm volatile("ldmatrix.sync.aligned.m8n8.x4.shared.b16 {%0,%1,%2,%3}, [%4];" \
                 : "=r"((r)[0]), "=r"((r)[1]), "=r"((r)[2]), "=r"((r)[3]) \
                 : "r"(addr))
#define LDSM_X2(r, addr) \
    asm volatile("ldmatrix.sync.aligned.m8n8.x2.shared.b16 {%0,%1}, [%2];" \
                 : "=r"((r)[0]), "=r"((r)[1]) : "r"(addr))
#define MMA16816(c, a, b) \
    asm volatile("mma.sync.aligned.m16n8k16.row.col.f32.bf16.bf16.f32 " \
                 "{%0,%1,%2,%3}, {%4,%5,%6,%7}, {%8,%9}, {%0,%1,%2,%3};" \
                 : "+f"((c)[0]), "+f"((c)[1]), "+f"((c)[2]), "+f"((c)[3]) \
                 : "r"((a)[0]), "r"((a)[1]), "r"((a)[2]), "r"((a)[3]), \
                   "r"((b)[0]), "r"((b)[1]))

__device__ __forceinline__ uint32_t pack_split(float f0, float f1, uint32_t& lo) {
    __nv_bfloat16 h0 = __float2bfloat16(f0);
    __nv_bfloat16 h1 = __float2bfloat16(f1);
    __nv_bfloat16 l0 = __float2bfloat16(f0 - __bfloat162float(h0));
    __nv_bfloat16 l1 = __float2bfloat16(f1 - __bfloat162float(h1));
    __nv_bfloat162 hp = __halves2bfloat162(h0, h1);
    __nv_bfloat162 lp = __halves2bfloat162(l0, l1);
    lo = *(uint32_t*)&lp;
    return *(uint32_t*)&hp;
}
__device__ __forceinline__ void split8(float4 a, float4 b, uint4& h, uint4& l) {
    h.x = pack_split(a.x, a.y, l.x);
    h.y = pack_split(a.z, a.w, l.y);
    h.z = pack_split(b.x, b.y, l.z);
    h.w = pack_split(b.z, b.w, l.w);
}

// ---------------------------------------------------------------------------
// Kernel 0: tsplit — sp (fp32 [s][k][d]) -> g_bfH/g_bfL (bf16, TRANSPOSED [s][d][k])
// ---------------------------------------------------------------------------
__global__ __launch_bounds__(256) void tsplit_kernel(const float* __restrict__ sp) {
    __shared__ unsigned short H[64][72];
    __shared__ unsigned short L[64][72];
    const int s = blockIdx.y;
    const int k0 = (blockIdx.x >> 2) * 64;
    const int d0 = (blockIdx.x & 3) * 64;
    const int t = threadIdx.x;
    const int r16 = t >> 4, c4 = (t & 15) * 4;

#pragma unroll
    for (int rr = 0; rr < 4; ++rr) {
        int kr = rr * 16 + r16;
        float4 v = *(const float4*)&sp[s * 65536 + (k0 + kr) * 256 + d0 + c4];
        uint32_t l01, l23;
        uint32_t h01 = pack_split(v.x, v.y, l01);
        uint32_t h23 = pack_split(v.z, v.w, l23);
        *(uint32_t*)&H[kr][c4]     = h01;
        *(uint32_t*)&H[kr][c4 + 2] = h23;
        *(uint32_t*)&L[kr][c4]     = l01;
        *(uint32_t*)&L[kr][c4 + 2] = l23;
    }
    __syncthreads();

    const int dr = t >> 2, q = t & 3;
#pragma unroll
    for (int h = 0; h < 2; ++h) {
        int kc = q * 16 + h * 8;
        uint32_t wh[4], wl[4];
#pragma unroll
        for (int j = 0; j < 4; ++j) {
            wh[j] = (uint32_t)H[kc + 2 * j][dr] | ((uint32_t)H[kc + 2 * j + 1][dr] << 16);
            wl[j] = (uint32_t)L[kc + 2 * j][dr] | ((uint32_t)L[kc + 2 * j + 1][dr] << 16);
        }
        int gi = s * 65536 + (d0 + dr) * 256 + k0 + kc;
        *(uint4*)&g_bfH[gi] = make_uint4(wh[0], wh[1], wh[2], wh[3]);
        *(uint4*)&g_bfL[gi] = make_uint4(wl[0], wl[1], wl[2], wl[3]);
    }
}

// ---------------------------------------------------------------------------
// Kernel 1: Gram via HMMA bf16 split. M[s] = Sp^T Sp, tiles (0,0),(1,0),(1,1).
// ---------------------------------------------------------------------------
#define ASTRIDE 72
#define ABUF (128 * ASTRIDE)
#define GEMM_SMEM (4 * ABUF * 2)

__global__ __launch_bounds__(256) void gram_mma_kernel() {
    extern __shared__ char shm[];
    __nv_bfloat16* AH = (__nv_bfloat16*)shm;
    __nv_bfloat16* AL = AH + ABUF;
    __nv_bfloat16* BH = AL + ABUF;
    __nv_bfloat16* BL = BH + ABUF;

    const int t = blockIdx.x;            // 0:(0,0) 1:(1,0) 2:(1,1)
    const int s = blockIdx.y;
    const int di = (t == 0) ? 0 : 1;
    const int ei = (t == 2) ? 1 : 0;
    const int tid = threadIdx.x;
    const int wid = tid >> 5, lane = tid & 31;
    const int wr = wid >> 2, wc = wid & 3;

    float c[4][4][4];
#pragma unroll
    for (int mt = 0; mt < 4; ++mt)
#pragma unroll
        for (int nt = 0; nt < 4; ++nt)
#pragma unroll
            for (int q = 0; q < 4; ++q) c[mt][nt][q] = 0.f;

    const int rowq = tid >> 1, half = tid & 1;
    const int sb = s * 65536;

    for (int ch = 0; ch < 4; ++ch) {
        const int k0 = ch * 64;
        __syncthreads();
#pragma unroll
        for (int j = 0; j < 4; ++j) {
            int kc = half * 32 + j * 8;
            int ga = sb + (di * 128 + rowq) * 256 + k0 + kc;
            int gb = sb + (ei * 128 + rowq) * 256 + k0 + kc;
            *(uint4*)(AH + rowq * ASTRIDE + kc) = *(const uint4*)&g_bfH[ga];
            *(uint4*)(AL + rowq * ASTRIDE + kc) = *(const uint4*)&g_bfL[ga];
            *(uint4*)(BH + rowq * ASTRIDE + kc) = *(const uint4*)&g_bfH[gb];
            *(uint4*)(BL + rowq * ASTRIDE + kc) = *(const uint4*)&g_bfL[gb];
        }
        __syncthreads();

        const int ar = lane & 15, as8 = (lane >> 4) * 8;
        const int br = lane & 7,  bs8 = ((lane >> 3) & 1) * 8;
#pragma unroll
        for (int ks = 0; ks < 4; ++ks) {
            const int kk = ks * 16;
            uint32_t bH[4][2], bL[4][2];
#pragma unroll
            for (int nt = 0; nt < 4; ++nt) {
                int row = wc * 32 + nt * 8 + br;
                LDSM_X2(bH[nt], smem_u32(BH + row * ASTRIDE + kk + bs8));
                LDSM_X2(bL[nt], smem_u32(BL + row * ASTRIDE + kk + bs8));
            }
#pragma unroll
            for (int mt = 0; mt < 4; ++mt) {
                int row = wr * 64 + mt * 16 + ar;
                uint32_t aH[4], aL[4];
                LDSM_X4(aH, smem_u32(AH + row * ASTRIDE + kk + as8));
                LDSM_X4(aL, smem_u32(AL + row * ASTRIDE + kk + as8));
#pragma unroll
                for (int nt = 0; nt < 4; ++nt) {
                    MMA16816(c[mt][nt], aH, bH[nt]);
                    MMA16816(c[mt][nt], aH, bL[nt]);
                    MMA16816(c[mt][nt], aL, bH[nt]);
                }
            }
        }
    }

    float* Cg = g_M + sb;
#pragma unroll
    for (int mt = 0; mt < 4; ++mt)
#pragma unroll
        for (int nt = 0; nt < 4; ++nt) {
            int r0 = di * 128 + wr * 64 + mt * 16 + (lane >> 2);
            int cc = ei * 128 + wc * 32 + nt * 8 + (lane & 3) * 2;
            *(float2*)&Cg[r0 * 256 + cc]       = make_float2(c[mt][nt][0], c[mt][nt][1]);
            *(float2*)&Cg[(r0 + 8) * 256 + cc] = make_float2(c[mt][nt][2], c[mt][nt][3]);
        }
}

// ---------------------------------------------------------------------------
// Kernel 2: blocked Cholesky + logdet + blocked inversion (identical to R14).
// ---------------------------------------------------------------------------
#define PPAD 68
#define P_FLOATS (256 * PPAD)
#define STG_FLOATS (64 * PPAD)
#define CHOL_SMEM_FLOATS (P_FLOATS + 2 * STG_FLOATS + 256)

__global__ __launch_bounds__(256) void cholinv_kernel() {
    extern __shared__ float sh[];
    float* P   = sh;
    float* As  = sh + P_FLOATS;
    float* Bs  = sh + P_FLOATS + STG_FLOATS;
    float* red = sh + P_FLOATS + 2 * STG_FLOATS;

    const int s = blockIdx.x;
    const int tid = threadIdx.x;
    const int sb = s * 65536;
    const float* Ms = g_M + sb;
    float* Mw = g_M + sb;
    float* LT = g_LT + sb;
    float* Wg = g_W + sb;

    const int rg = (tid >> 4) * 4;
    const int cg = (tid & 15) * 4;

    red[tid] = Ms[tid * D_ + tid];
    __syncthreads();
    for (int o = 128; o > 0; o >>= 1) {
        if (tid < o) red[tid] += red[tid + o];
        __syncthreads();
    }
    const float ridge = 0.01f * red[0] / (float)D_;
    __syncthreads();

    for (int J = 0; J < 4; ++J) {
        const int R = 256 - 64 * J;
        const int g0 = 64 * J;

        for (int e = tid; e < R * 16; e += 256) {
            int pr = e >> 4, c4 = (e & 15) * 4;
            float4 v = *(const float4*)&Ms[(g0 + pr) * D_ + g0 + c4];
            *(float4*)&P[pr * PPAD + c4] = v;
        }
        __syncthreads();
        if (tid < 64) P[tid * PPAD + tid] += ridge;
        __syncthreads();

        for (int K = 0; K < J; ++K) {
            __syncthreads();
            for (int e = tid; e < 1024; e += 256) {
                int k = e >> 4, c4 = (e & 15) * 4;
                float4 v = *(const float4*)&LT[(64 * K + k) * D_ + g0 + c4];
                *(float4*)&Bs[k * PPAD + c4] = v;
            }
            for (int I = J; I < 4; ++I) {
                __syncthreads();
                for (int e = tid; e < 1024; e += 256) {
                    int k = e >> 4, r4 = (e & 15) * 4;
                    float4 v = *(const float4*)&LT[(64 * K + k) * D_ + 64 * I + r4];
                    *(float4*)&As[k * PPAD + r4] = v;
                }
                __syncthreads();
                float acc[4][4];
#pragma unroll
                for (int r = 0; r < 4; ++r)
#pragma unroll
                    for (int c = 0; c < 4; ++c) acc[r][c] = 0.f;
#pragma unroll 4
                for (int kk = 0; kk < 64; ++kk) {
                    float4 a = *(const float4*)&As[kk * PPAD + rg];
                    float4 b = *(const float4*)&Bs[kk * PPAD + cg];
                    float av[4] = {a.x, a.y, a.z, a.w};
                    float bv[4] = {b.x, b.y, b.z, b.w};
#pragma unroll
                    for (int r = 0; r < 4; ++r)
#pragma unroll
                        for (int c = 0; c < 4; ++c) acc[r][c] += av[r] * bv[c];
                }
                const int prb = 64 * (I - J);
#pragma unroll
                for (int r = 0; r < 4; ++r)
#pragma unroll
                    for (int c = 0; c < 4; ++c)
                        P[(prb + rg + r) * PPAD + cg + c] -= acc[r][c];
            }
        }
        __syncthreads();

        for (int jj = 0; jj < 64; ++jj) {
            const int pr = jj + tid;
            const bool act = pr < R;
            float num = 0.f;
            if (act) {
                const float* rp = P + pr * PPAD;
                const float* rj = P + jj * PPAD;
                float a0 = 0.f, a1 = 0.f, a2 = 0.f, a3 = 0.f;
                const int j4 = jj & ~3;
                for (int k = 0; k < j4; k += 4) {
                    float4 u = *(const float4*)(rp + k);
                    float4 v = *(const float4*)(rj + k);
                    a0 += u.x * v.x; a1 += u.y * v.y;
                    a2 += u.z * v.z; a3 += u.w * v.w;
                }
                for (int k = j4; k < jj; ++k) a0 += rp[k] * rj[k];
                num = rp[jj] - ((a0 + a1) + (a2 + a3));
            }
            if (tid == 0) red[0] = num;
            __syncthreads();
            const float dj = sqrtf(red[0]);
            if (act) P[pr * PPAD + jj] = (tid == 0) ? dj : num / dj;
            __syncthreads();
        }

        for (int e = tid; e < R * 16; e += 256) {
            int pr = e >> 4, c4 = (e & 15) * 4;
            float4 v = *(const float4*)&P[pr * PPAD + c4];
            *(float4*)&Mw[(g0 + pr) * D_ + g0 + c4] = v;
        }
        for (int c = 0; c < 64; ++c) {
            for (int pr = tid; pr < R; pr += 256)
                LT[(g0 + c) * D_ + g0 + pr] = P[pr * PPAD + c];
        }
        __syncthreads();
    }

    red[tid] = 2.f * logf(Mw[tid * D_ + tid]);
    __syncthreads();
    for (int o = 128; o > 0; o >>= 1) {
        if (tid < o) red[tid] += red[tid + o];
        __syncthreads();
    }
    if (tid == 0) g_logdet[s] = red[0];
    __syncthreads();

    for (int t = tid; t < 16384; t += 256) P[t] = 0.f;
    __syncthreads();

    for (int rnd = 0; rnd < 2; ++rnd) {
        for (int e = tid; e < 1024; e += 256) {
            int ii = e >> 4, t4 = (e & 15) * 4;
            int K0 = 2 * rnd, K1 = 2 * rnd + 1;
            *(float4*)&As[ii * 64 + t4] =
                *(const float4*)&Mw[(64 * K0 + ii) * D_ + 64 * K0 + t4];
            *(float4*)&Bs[ii * 64 + t4] =
                *(const float4*)&Mw[(64 * K1 + ii) * D_ + 64 * K1 + t4];
        }
        __syncthreads();
        if (tid < 128) {
            const int g = tid >> 6;
            const int jj = tid & 63;
            const int K = 2 * rnd + g;
            float* WK = P + K * 4096;
            const float* Ld = g ? Bs : As;
            for (int ii = jj; ii < 64; ++ii) {
                float acc = (ii == jj) ? 1.f : 0.f;
                for (int t = jj; t < ii; ++t) acc -= Ld[ii * 64 + t] * WK[t * 64 + jj];
                WK[ii * 64 + jj] = acc / Ld[ii * 64 + ii];
            }
        }
        __syncthreads();
    }

    for (int e = tid; e < 8192; e += 256) {
        int Kb = e >> 11, rr = (e >> 5) & 63, c2 = (e & 31) * 2;
        float v0 = P[Kb * 4096 + rr * 64 + c2];
        float v1 = P[Kb * 4096 + rr * 64 + c2 + 1];
        int gi = (64 * Kb + rr) * D_ + 64 * Kb + c2;
        Wg[gi] = v0; Wg[gi + 1] = v1;
        uint32_t lo, hi = pack_split(v0, v1, lo);
        *(uint32_t*)&g_bfH[sb + gi] = hi;
        *(uint32_t*)&g_bfL[sb + gi] = lo;
    }
    for (int e = tid; e < 6 * 2048; e += 256) {
        int bb = e >> 11, rr = (e >> 5) & 63, c2 = (e & 31) * 2;
        int I = (bb < 3) ? 0 : ((bb < 5) ? 1 : 2);
        int J = (bb < 3) ? (bb + 1) : ((bb == 3) ? 2 : 3);
        int gi = (64 * I + rr) * D_ + 64 * J + c2;
        Wg[gi] = 0.f; Wg[gi + 1] = 0.f;
        *(uint32_t*)&g_bfH[sb + gi] = 0u;
        *(uint32_t*)&g_bfL[sb + gi] = 0u;
    }
    __syncthreads();

    for (int J = 0; J < 3; ++J) {
        for (int I = J + 1; I < 4; ++I) {
            float acc[4][4];
#pragma unroll
            for (int r = 0; r < 4; ++r)
#pragma unroll
                for (int c = 0; c < 4; ++c) acc[r][c] = 0.f;

            for (int K = J; K < I; ++K) {
                __syncthreads();
                for (int e = tid; e < 1024; e += 256) {
                    int k = e >> 4, r4 = (e & 15) * 4;
                    float4 v = *(const float4*)&LT[(64 * K + k) * D_ + 64 * I + r4];
                    *(float4*)&As[k * PPAD + r4] = v;
                }
                for (int e = tid; e < 1024; e += 256) {
                    int k = e >> 4, c4 = (e & 15) * 4;
                    float4 v;
                    if (K == J) {
                        v = make_float4(P[J * 4096 + k * 64 + c4 + 0],
                                        P[J * 4096 + k * 64 + c4 + 1],
                                        P[J * 4096 + k * 64 + c4 + 2],
                                        P[J * 4096 + k * 64 + c4 + 3]);
                    } else {
                        v = *(const float4*)&Wg[(64 * K + k) * D_ + 64 * J + c4];
                    }
                    *(float4*)&Bs[k * PPAD + c4] = v;
                }
                __syncthreads();
#pragma unroll 4
                for (int kk = 0; kk < 64; ++kk) {
                    float4 a = *(const float4*)&As[kk * PPAD + rg];
                    float4 b = *(const float4*)&Bs[kk * PPAD + cg];
                    float av[4] = {a.x, a.y, a.z, a.w};
                    float bv[4] = {b.x, b.y, b.z, b.w};
#pragma unroll
                    for (int r = 0; r < 4; ++r)
#pragma unroll
                        for (int c = 0; c < 4; ++c) acc[r][c] += av[r] * bv[c];
                }
            }
            __syncthreads();
#pragma unroll
            for (int r = 0; r < 4; ++r)
#pragma unroll
                for (int c = 0; c < 4; ++c)
                    Bs[(rg + r) * PPAD + cg + c] = acc[r][c];
            __syncthreads();
            float o[4][4];
#pragma unroll
            for (int r = 0; r < 4; ++r)
#pragma unroll
                for (int c = 0; c < 4; ++c) o[r][c] = 0.f;
            const float* wA = P + I * 4096;
#pragma unroll 4
            for (int kk = 0; kk < 64; ++kk) {
                float av[4];
#pragma unroll
                for (int r = 0; r < 4; ++r) av[r] = wA[(rg + r) * 64 + kk];
                float4 b = *(const float4*)&Bs[kk * PPAD + cg];
                float bv[4] = {b.x, b.y, b.z, b.w};
#pragma unroll
                for (int r = 0; r < 4; ++r)
#pragma unroll
                    for (int c = 0; c < 4; ++c) o[r][c] += av[r] * bv[c];
            }
#pragma unroll
            for (int r = 0; r < 4; ++r) {
                float n0 = -o[r][0], n1 = -o[r][1], n2 = -o[r][2], n3 = -o[r][3];
                int gi = (64 * I + rg + r) * D_ + 64 * J + cg;
                *(float4*)&Wg[gi] = make_float4(n0, n1, n2, n3);
                uint32_t l01, l23;
                uint32_t h01 = pack_split(n0, n1, l01);
                uint32_t h23 = pack_split(n2, n3, l23);
                *(uint2*)&g_bfH[sb + gi] = make_uint2(h01, h23);
                *(uint2*)&g_bfL[sb + gi] = make_uint2(l01, l23);
            }
        }
    }
}

// ---------------------------------------------------------------------------
// Kernel 3: maha via mma.sync bf16 split GEMM + square-reduce epilogue.
// R14 structure, but 2 CTAs/SM (__launch_bounds__(256,2), smem 74.8KB) and
// a-fragments loaded per-mt inside the MMA loop (<=128 regs, no spill).
// ---------------------------------------------------------------------------
#define MAHA_SMEM (4 * ABUF * 2 + 256 * 4)

__global__ __launch_bounds__(256, 2) void maha_mma_kernel(const float* __restrict__ x,
                                                          const float* __restrict__ mu,
                                                          float* __restrict__ out) {
    extern __shared__ char shm[];
    __nv_bfloat16* AH = (__nv_bfloat16*)shm;
    __nv_bfloat16* AL = AH + ABUF;
    __nv_bfloat16* BH = AL + ABUF;
    __nv_bfloat16* BL = BH + ABUF;
    float* sacc = (float*)(shm + 4 * ABUF * 2);   // [2 warp-rows][128 cols]

    const int s = blockIdx.y;
    const int b0 = blockIdx.x * 128;
    const int tid = threadIdx.x;
    const int wid = tid >> 5, lane = tid & 31;
    const int wr = wid >> 2;
    const int wc = wid & 3;

    sacc[tid] = 0.f;
    __syncthreads();

    const int sb = s * 65536;
    const int srow = tid >> 3;              // 0..31 (B staging row group)
    const int sk8  = (tid & 7) * 8;
    const int rowq = tid >> 1, half = tid & 1;   // A staging

    for (int dt = 0; dt < 2; ++dt) {
        float c[4][4][4];
#pragma unroll
        for (int mt = 0; mt < 4; ++mt)
#pragma unroll
            for (int nt = 0; nt < 4; ++nt)
#pragma unroll
                for (int q = 0; q < 4; ++q) c[mt][nt][q] = 0.f;

        const int nch = dt ? 4 : 2;          // d-tile 0: W zero beyond k=128
        for (int ch = 0; ch < nch; ++ch) {
            const int k0 = ch * 64;
            __syncthreads();
            // ---- stage A: direct bf16 copies from g_bfH/g_bfL ----
#pragma unroll
            for (int j = 0; j < 4; ++j) {
                int kc = half * 32 + j * 8;
                int ga = sb + (dt * 128 + rowq) * 256 + k0 + kc;
                *(uint4*)(AH + rowq * ASTRIDE + kc) = *(const uint4*)&g_bfH[ga];
                *(uint4*)(AL + rowq * ASTRIDE + kc) = *(const uint4*)&g_bfL[ga];
            }
            // ---- stage B = x[b0+row] - mu[s], split on the fly ----
#pragma unroll
            for (int it = 0; it < 4; ++it) {
                int row = srow + it * 32;
                const float* px = x + (b0 + row) * 256 + k0 + sk8;
                const float* pm = mu + s * 256 + k0 + sk8;
                float4 u = *(const float4*)px;
                float4 um = *(const float4*)pm;
                float4 v = *(const float4*)(px + 4);
                float4 vm = *(const float4*)(pm + 4);
                u.x -= um.x; u.y -= um.y; u.z -= um.z; u.w -= um.w;
                v.x -= vm.x; v.y -= vm.y; v.z -= vm.z; v.w -= vm.w;
                uint4 hq, lq; split8(u, v, hq, lq);
                *(uint4*)(BH + row * ASTRIDE + sk8) = hq;
                *(uint4*)(BL + row * ASTRIDE + sk8) = lq;
            }
            __syncthreads();

            const int ar = lane & 15, as8 = (lane >> 4) * 8;
            const int br = lane & 7,  bs8 = ((lane >> 3) & 1) * 8;
#pragma unroll
            for (int ks = 0; ks < 4; ++ks) {
                const int kk = ks * 16;
                uint32_t bH[4][2], bL[4][2];
#pragma unroll
                for (int nt = 0; nt < 4; ++nt) {
                    int row = wc * 32 + nt * 8 + br;
                    LDSM_X2(bH[nt], smem_u32(BH + row * ASTRIDE + kk + bs8));
                    LDSM_X2(bL[nt], smem_u32(BL + row * ASTRIDE + kk + bs8));
                }
#pragma unroll
                for (int mt = 0; mt < 4; ++mt) {
                    int row = wr * 64 + mt * 16 + ar;
                    uint32_t aH[4], aL[4];
                    LDSM_X4(aH, smem_u32(AH + row * ASTRIDE + kk + as8));
                    LDSM_X4(aL, smem_u32(AL + row * ASTRIDE + kk + as8));
#pragma unroll
                    for (int nt = 0; nt < 4; ++nt) {
                        MMA16816(c[mt][nt], aH, bH[nt]);
                        MMA16816(c[mt][nt], aH, bL[nt]);
                        MMA16816(c[mt][nt], aL, bH[nt]);
                    }
                }
            }
        }

        // ---- epilogue: square + reduce over d within warp, slot-accumulate ----
#pragma unroll
        for (int nt = 0; nt < 4; ++nt) {
            float p0 = 0.f, p1 = 0.f;
#pragma unroll
            for (int mt = 0; mt < 4; ++mt) {
                p0 += c[mt][nt][0] * c[mt][nt][0] + c[mt][nt][2] * c[mt][nt][2];
                p1 += c[mt][nt][1] * c[mt][nt][1] + c[mt][nt][3] * c[mt][nt][3];
            }
#pragma unroll
            for (int m = 4; m <= 16; m <<= 1) {
                p0 += __shfl_xor_sync(0xffffffffu, p0, m);
                p1 += __shfl_xor_sync(0xffffffffu, p1, m);
            }
            if (lane < 4) {
                int col = wc * 32 + nt * 8 + 2 * lane;
                sacc[wr * 128 + col]     += p0;
                sacc[wr * 128 + col + 1] += p1;
            }
        }
    }

    __syncthreads();
    if (tid < 128) {
        float m = sacc[tid] + sacc[128 + tid];
        out[(b0 + tid) * S_ + s] = -0.5f * ((float)D_ * LOG2PI + g_logdet[s] + m);
    }
}

// ---------------------------------------------------------------------------
extern "C" void kernel_launch(void* const* d_in, const int* in_sizes, int n_in,
                              void* d_out, int out_size) {
    const float* x  = (const float*)d_in[0];   // (B, D)
    const float* mu = (const float*)d_in[1];   // (S, 1, D)
    const float* sp = (const float*)d_in[2];   // (S, 1, D, D)
    float* out = (float*)d_out;                // (B, S)

    const int chol_smem = CHOL_SMEM_FLOATS * sizeof(float);   // 105,472 B
    cudaFuncSetAttribute(cholinv_kernel,
                         cudaFuncAttributeMaxDynamicSharedMemorySize, chol_smem);
    cudaFuncSetAttribute(gram_mma_kernel,
                         cudaFuncAttributeMaxDynamicSharedMemorySize, GEMM_SMEM);
    cudaFuncSetAttribute(maha_mma_kernel,
                         cudaFuncAttributeMaxDynamicSharedMemorySize, MAHA_SMEM);

    tsplit_kernel<<<dim3(16, S_), 256>>>(sp);
    gram_mma_kernel<<<dim3(3, S_), 256, GEMM_SMEM>>>();
    cholinv_kernel<<<S_, 256, chol_smem>>>();
    maha_mma_kernel<<<dim3(B_ / 128, S_), 256, MAHA_SMEM>>>(x, mu, out);
}

// round 17
// speedup vs baseline: 1.8054x; 1.0381x over previous
#include <cuda_runtime.h>
#include <cuda_bf16.h>
#include <math.h>
#include <stdint.h>

#define S_ 256
#define D_ 256
#define B_ 1024
#define LOG2PI 1.8378770664093453f

// Scratch (no runtime allocation allowed)
__device__ float g_M[S_ * D_ * D_];    // Gram -> overwritten in place by L (lower)
__device__ float g_LT[S_ * D_ * D_];   // L transposed (k-major), lower part valid
__device__ float g_W[S_ * D_ * D_];    // W = L^{-1} fp32 (used inside cholinv)
__device__ float g_logdet[S_];
// bf16 hi/lo split arrays, time-multiplexed:
//  phase 1: transposed sp ([s][d][k]) for gram
//  phase 2: L rows ([s][row][col]) during cholinv factorization (history HMMA)
//  phase 3: W ([s][row][col]) for maha (overwrites all of phase 2)
__device__ __nv_bfloat16 g_bfH[S_ * D_ * D_];
__device__ __nv_bfloat16 g_bfL[S_ * D_ * D_];

// ---------------------------------------------------------------------------
// helpers
// ---------------------------------------------------------------------------
__device__ __forceinline__ uint32_t smem_u32(const void* p) {
    uint32_t a;
    asm("{ .reg .u64 t; cvta.to.shared.u64 t, %1; cvt.u32.u64 %0, t; }"
        : "=r"(a) : "l"(p));
    return a;
}
#define LDSM_X4(r, addr) \
    asm volatile("ldmatrix.sync.aligned.m8n8.x4.shared.b16 {%0,%1,%2,%3}, [%4];" \
                 : "=r"((r)[0]), "=r"((r)[1]), "=r"((r)[2]), "=r"((r)[3]) \
                 : "r"(addr))
#define LDSM_X2(r, addr) \
    asm volatile("ldmatrix.sync.aligned.m8n8.x2.shared.b16 {%0,%1}, [%2];" \
                 : "=r"((r)[0]), "=r"((r)[1]) : "r"(addr))
#define MMA16816(c, a, b) \
    asm volatile("mma.sync.aligned.m16n8k16.row.col.f32.bf16.bf16.f32 " \
                 "{%0,%1,%2,%3}, {%4,%5,%6,%7}, {%8,%9}, {%0,%1,%2,%3};" \
                 : "+f"((c)[0]), "+f"((c)[1]), "+f"((c)[2]), "+f"((c)[3]) \
                 : "r"((a)[0]), "r"((a)[1]), "r"((a)[2]), "r"((a)[3]), \
                   "r"((b)[0]), "r"((b)[1]))

__device__ __forceinline__ uint32_t pack_split(float f0, float f1, uint32_t& lo) {
    __nv_bfloat16 h0 = __float2bfloat16(f0);
    __nv_bfloat16 h1 = __float2bfloat16(f1);
    __nv_bfloat16 l0 = __float2bfloat16(f0 - __bfloat162float(h0));
    __nv_bfloat16 l1 = __float2bfloat16(f1 - __bfloat162float(h1));
    __nv_bfloat162 hp = __halves2bfloat162(h0, h1);
    __nv_bfloat162 lp = __halves2bfloat162(l0, l1);
    lo = *(uint32_t*)&lp;
    return *(uint32_t*)&hp;
}
__device__ __forceinline__ void split8(float4 a, float4 b, uint4& h, uint4& l) {
    h.x = pack_split(a.x, a.y, l.x);
    h.y = pack_split(a.z, a.w, l.y);
    h.z = pack_split(b.x, b.y, l.z);
    h.w = pack_split(b.z, b.w, l.w);
}

// ---------------------------------------------------------------------------
// Kernel 0: tsplit — sp (fp32 [s][k][d]) -> g_bfH/g_bfL (bf16, TRANSPOSED [s][d][k])
// ---------------------------------------------------------------------------
__global__ __launch_bounds__(256) void tsplit_kernel(const float* __restrict__ sp) {
    __shared__ unsigned short H[64][72];
    __shared__ unsigned short L[64][72];
    const int s = blockIdx.y;
    const int k0 = (blockIdx.x >> 2) * 64;
    const int d0 = (blockIdx.x & 3) * 64;
    const int t = threadIdx.x;
    const int r16 = t >> 4, c4 = (t & 15) * 4;

#pragma unroll
    for (int rr = 0; rr < 4; ++rr) {
        int kr = rr * 16 + r16;
        float4 v = *(const float4*)&sp[s * 65536 + (k0 + kr) * 256 + d0 + c4];
        uint32_t l01, l23;
        uint32_t h01 = pack_split(v.x, v.y, l01);
        uint32_t h23 = pack_split(v.z, v.w, l23);
        *(uint32_t*)&H[kr][c4]     = h01;
        *(uint32_t*)&H[kr][c4 + 2] = h23;
        *(uint32_t*)&L[kr][c4]     = l01;
        *(uint32_t*)&L[kr][c4 + 2] = l23;
    }
    __syncthreads();

    const int dr = t >> 2, q = t & 3;
#pragma unroll
    for (int h = 0; h < 2; ++h) {
        int kc = q * 16 + h * 8;
        uint32_t wh[4], wl[4];
#pragma unroll
        for (int j = 0; j < 4; ++j) {
            wh[j] = (uint32_t)H[kc + 2 * j][dr] | ((uint32_t)H[kc + 2 * j + 1][dr] << 16);
            wl[j] = (uint32_t)L[kc + 2 * j][dr] | ((uint32_t)L[kc + 2 * j + 1][dr] << 16);
        }
        int gi = s * 65536 + (d0 + dr) * 256 + k0 + kc;
        *(uint4*)&g_bfH[gi] = make_uint4(wh[0], wh[1], wh[2], wh[3]);
        *(uint4*)&g_bfL[gi] = make_uint4(wl[0], wl[1], wl[2], wl[3]);
    }
}

// ---------------------------------------------------------------------------
// Kernel 1: Gram via HMMA bf16 split. M[s] = Sp^T Sp, tiles (0,0),(1,0),(1,1).
// ---------------------------------------------------------------------------
#define ASTRIDE 72
#define ABUF (128 * ASTRIDE)
#define GEMM_SMEM (4 * ABUF * 2)

__global__ __launch_bounds__(256) void gram_mma_kernel() {
    extern __shared__ char shm[];
    __nv_bfloat16* AH = (__nv_bfloat16*)shm;
    __nv_bfloat16* AL = AH + ABUF;
    __nv_bfloat16* BH = AL + ABUF;
    __nv_bfloat16* BL = BH + ABUF;

    const int t = blockIdx.x;            // 0:(0,0) 1:(1,0) 2:(1,1)
    const int s = blockIdx.y;
    const int di = (t == 0) ? 0 : 1;
    const int ei = (t == 2) ? 1 : 0;
    const int tid = threadIdx.x;
    const int wid = tid >> 5, lane = tid & 31;
    const int wr = wid >> 2, wc = wid & 3;

    float c[4][4][4];
#pragma unroll
    for (int mt = 0; mt < 4; ++mt)
#pragma unroll
        for (int nt = 0; nt < 4; ++nt)
#pragma unroll
            for (int q = 0; q < 4; ++q) c[mt][nt][q] = 0.f;

    const int rowq = tid >> 1, half = tid & 1;
    const int sb = s * 65536;

    for (int ch = 0; ch < 4; ++ch) {
        const int k0 = ch * 64;
        __syncthreads();
#pragma unroll
        for (int j = 0; j < 4; ++j) {
            int kc = half * 32 + j * 8;
            int ga = sb + (di * 128 + rowq) * 256 + k0 + kc;
            int gb = sb + (ei * 128 + rowq) * 256 + k0 + kc;
            *(uint4*)(AH + rowq * ASTRIDE + kc) = *(const uint4*)&g_bfH[ga];
            *(uint4*)(AL + rowq * ASTRIDE + kc) = *(const uint4*)&g_bfL[ga];
            *(uint4*)(BH + rowq * ASTRIDE + kc) = *(const uint4*)&g_bfH[gb];
            *(uint4*)(BL + rowq * ASTRIDE + kc) = *(const uint4*)&g_bfL[gb];
        }
        __syncthreads();

        const int ar = lane & 15, as8 = (lane >> 4) * 8;
        const int br = lane & 7,  bs8 = ((lane >> 3) & 1) * 8;
#pragma unroll
        for (int ks = 0; ks < 4; ++ks) {
            const int kk = ks * 16;
            uint32_t bH[4][2], bL[4][2];
#pragma unroll
            for (int nt = 0; nt < 4; ++nt) {
                int row = wc * 32 + nt * 8 + br;
                LDSM_X2(bH[nt], smem_u32(BH + row * ASTRIDE + kk + bs8));
                LDSM_X2(bL[nt], smem_u32(BL + row * ASTRIDE + kk + bs8));
            }
#pragma unroll
            for (int mt = 0; mt < 4; ++mt) {
                int row = wr * 64 + mt * 16 + ar;
                uint32_t aH[4], aL[4];
                LDSM_X4(aH, smem_u32(AH + row * ASTRIDE + kk + as8));
                LDSM_X4(aL, smem_u32(AL + row * ASTRIDE + kk + as8));
#pragma unroll
                for (int nt = 0; nt < 4; ++nt) {
                    MMA16816(c[mt][nt], aH, bH[nt]);
                    MMA16816(c[mt][nt], aH, bL[nt]);
                    MMA16816(c[mt][nt], aL, bH[nt]);
                }
            }
        }
    }

    float* Cg = g_M + sb;
#pragma unroll
    for (int mt = 0; mt < 4; ++mt)
#pragma unroll
        for (int nt = 0; nt < 4; ++nt) {
            int r0 = di * 128 + wr * 64 + mt * 16 + (lane >> 2);
            int cc = ei * 128 + wc * 32 + nt * 8 + (lane & 3) * 2;
            *(float2*)&Cg[r0 * 256 + cc]       = make_float2(c[mt][nt][0], c[mt][nt][1]);
            *(float2*)&Cg[(r0 + 8) * 256 + cc] = make_float2(c[mt][nt][2], c[mt][nt][3]);
        }
}

// ---------------------------------------------------------------------------
// Kernel 2: blocked Cholesky + logdet + blocked inversion.
// NEW: history updates (P -= L(:,K)·L(J,K)^T) now run on HMMA bf16-split,
// reading L-split rows written to g_bfH/g_bfL during panel writeback.
// smem: P (17408 f) | U union (9216 f: fp32 As/Bs for PhaseA/B, bf16 4x64x72
// staging for history) | red (256 f) = 107,520 B -> 2 blocks/SM.
// ---------------------------------------------------------------------------
#define PPAD 68
#define P_FLOATS (256 * PPAD)
#define STG_FLOATS (64 * PPAD)
#define UNION_FLOATS 9216
#define CHOL_SMEM_FLOATS (P_FLOATS + UNION_FLOATS + 256)
#define HSTR 72                       // bf16 staging row stride (144 B)

__global__ __launch_bounds__(256) void cholinv_kernel() {
    extern __shared__ float sh[];
    float* P   = sh;
    float* U   = sh + P_FLOATS;                 // union region
    float* red = sh + P_FLOATS + UNION_FLOATS;

    float* As = U;                              // fp32 staging (Phase A/B)
    float* Bs = U + STG_FLOATS;
    __nv_bfloat16* uAH = (__nv_bfloat16*)U;     // bf16 staging (history HMMA)
    __nv_bfloat16* uAL = uAH + 64 * HSTR;
    __nv_bfloat16* uBH = uAL + 64 * HSTR;
    __nv_bfloat16* uBL = uBH + 64 * HSTR;

    const int s = blockIdx.x;
    const int tid = threadIdx.x;
    const int sb = s * 65536;
    const float* Ms = g_M + sb;
    float* Mw = g_M + sb;
    float* LT = g_LT + sb;
    float* Wg = g_W + sb;

    const int rg = (tid >> 4) * 4;
    const int cg = (tid & 15) * 4;
    const int wid = tid >> 5, lane = tid & 31;
    const int wr = wid >> 2, wc = wid & 3;      // 2x4 warp grid for history

    red[tid] = Ms[tid * D_ + tid];
    __syncthreads();
    for (int o = 128; o > 0; o >>= 1) {
        if (tid < o) red[tid] += red[tid + o];
        __syncthreads();
    }
    const float ridge = 0.01f * red[0] / (float)D_;
    __syncthreads();

    for (int J = 0; J < 4; ++J) {
        const int R = 256 - 64 * J;
        const int g0 = 64 * J;

        for (int e = tid; e < R * 16; e += 256) {
            int pr = e >> 4, c4 = (e & 15) * 4;
            float4 v = *(const float4*)&Ms[(g0 + pr) * D_ + g0 + c4];
            *(float4*)&P[pr * PPAD + c4] = v;
        }
        __syncthreads();
        if (tid < 64) P[tid * PPAD + tid] += ridge;
        __syncthreads();

        // ---- history update via 3-pass HMMA: P -= L(:,K) * L(J,K)^T ----
        {
            const int srow = tid >> 2, skq = (tid & 3) * 16;   // staging map
            const int ar = lane & 15, as8 = (lane >> 4) * 8;
            const int br = lane & 7,  bs8 = ((lane >> 3) & 1) * 8;
            for (int K = 0; K < J; ++K) {
                __syncthreads();   // prior MMA (or panel load) done before restage
                // stage B: rows g0+c of L, cols 64K..64K+63
                {
                    int gi = sb + (g0 + srow) * 256 + 64 * K + skq;
                    *(uint4*)(uBH + srow * HSTR + skq)     = *(const uint4*)&g_bfH[gi];
                    *(uint4*)(uBH + srow * HSTR + skq + 8) = *(const uint4*)&g_bfH[gi + 8];
                    *(uint4*)(uBL + srow * HSTR + skq)     = *(const uint4*)&g_bfL[gi];
                    *(uint4*)(uBL + srow * HSTR + skq + 8) = *(const uint4*)&g_bfL[gi + 8];
                }
                for (int I = J; I < 4; ++I) {
                    __syncthreads();   // B staged / prior MMA done
                    // stage A: rows 64I+r of L, cols 64K..64K+63
                    {
                        int gi = sb + (64 * I + srow) * 256 + 64 * K + skq;
                        *(uint4*)(uAH + srow * HSTR + skq)     = *(const uint4*)&g_bfH[gi];
                        *(uint4*)(uAH + srow * HSTR + skq + 8) = *(const uint4*)&g_bfH[gi + 8];
                        *(uint4*)(uAL + srow * HSTR + skq)     = *(const uint4*)&g_bfL[gi];
                        *(uint4*)(uAL + srow * HSTR + skq + 8) = *(const uint4*)&g_bfL[gi + 8];
                    }
                    __syncthreads();

                    float cf[2][2][4];
#pragma unroll
                    for (int mt = 0; mt < 2; ++mt)
#pragma unroll
                        for (int nt = 0; nt < 2; ++nt)
#pragma unroll
                            for (int q = 0; q < 4; ++q) cf[mt][nt][q] = 0.f;

#pragma unroll
                    for (int ks = 0; ks < 4; ++ks) {
                        const int kk = ks * 16;
                        uint32_t bH[2][2], bL[2][2];
#pragma unroll
                        for (int nt = 0; nt < 2; ++nt) {
                            int row = wc * 16 + nt * 8 + br;
                            LDSM_X2(bH[nt], smem_u32(uBH + row * HSTR + kk + bs8));
                            LDSM_X2(bL[nt], smem_u32(uBL + row * HSTR + kk + bs8));
                        }
#pragma unroll
                        for (int mt = 0; mt < 2; ++mt) {
                            int row = wr * 32 + mt * 16 + ar;
                            uint32_t aH[4], aL[4];
                            LDSM_X4(aH, smem_u32(uAH + row * HSTR + kk + as8));
                            LDSM_X4(aL, smem_u32(uAL + row * HSTR + kk + as8));
#pragma unroll
                            for (int nt = 0; nt < 2; ++nt) {
                                MMA16816(cf[mt][nt], aH, bH[nt]);
                                MMA16816(cf[mt][nt], aH, bL[nt]);
                                MMA16816(cf[mt][nt], aL, bH[nt]);
                            }
                        }
                    }
                    // subtract frags into panel P
                    const int prb = 64 * (I - J);
#pragma unroll
                    for (int mt = 0; mt < 2; ++mt)
#pragma unroll
                        for (int nt = 0; nt < 2; ++nt) {
                            int r0 = prb + wr * 32 + mt * 16 + (lane >> 2);
                            int cc = wc * 16 + nt * 8 + (lane & 3) * 2;
                            float2 p0 = *(float2*)&P[r0 * PPAD + cc];
                            p0.x -= cf[mt][nt][0]; p0.y -= cf[mt][nt][1];
                            *(float2*)&P[r0 * PPAD + cc] = p0;
                            float2 p1 = *(float2*)&P[(r0 + 8) * PPAD + cc];
                            p1.x -= cf[mt][nt][2]; p1.y -= cf[mt][nt][3];
                            *(float2*)&P[(r0 + 8) * PPAD + cc] = p1;
                        }
                }
            }
        }
        __syncthreads();

        // ---- factor the 64-wide panel (left-looking within panel) ----
        for (int jj = 0; jj < 64; ++jj) {
            const int pr = jj + tid;
            const bool act = pr < R;
            float num = 0.f;
            if (act) {
                const float* rp = P + pr * PPAD;
                const float* rj = P + jj * PPAD;
                float a0 = 0.f, a1 = 0.f, a2 = 0.f, a3 = 0.f;
                const int j4 = jj & ~3;
                for (int k = 0; k < j4; k += 4) {
                    float4 u = *(const float4*)(rp + k);
                    float4 v = *(const float4*)(rj + k);
                    a0 += u.x * v.x; a1 += u.y * v.y;
                    a2 += u.z * v.z; a3 += u.w * v.w;
                }
                for (int k = j4; k < jj; ++k) a0 += rp[k] * rj[k];
                num = rp[jj] - ((a0 + a1) + (a2 + a3));
            }
            if (tid == 0) red[0] = num;
            __syncthreads();
            const float dj = sqrtf(red[0]);
            if (act) P[pr * PPAD + jj] = (tid == 0) ? dj : num / dj;
            __syncthreads();
        }

        // write panel back: g_M (row-major), g_LT (k-major), Lbf split (row-major)
        for (int e = tid; e < R * 16; e += 256) {
            int pr = e >> 4, c4 = (e & 15) * 4;
            float4 v = *(const float4*)&P[pr * PPAD + c4];
            *(float4*)&Mw[(g0 + pr) * D_ + g0 + c4] = v;
            uint32_t l01, l23;
            uint32_t h01 = pack_split(v.x, v.y, l01);
            uint32_t h23 = pack_split(v.z, v.w, l23);
            int gi = sb + (g0 + pr) * 256 + g0 + c4;
            *(uint2*)&g_bfH[gi] = make_uint2(h01, h23);
            *(uint2*)&g_bfL[gi] = make_uint2(l01, l23);
        }
        for (int c = 0; c < 64; ++c) {
            for (int pr = tid; pr < R; pr += 256)
                LT[(g0 + c) * D_ + g0 + pr] = P[pr * PPAD + c];
        }
        __syncthreads();
    }

    red[tid] = 2.f * logf(Mw[tid * D_ + tid]);
    __syncthreads();
    for (int o = 128; o > 0; o >>= 1) {
        if (tid < o) red[tid] += red[tid + o];
        __syncthreads();
    }
    if (tid == 0) g_logdet[s] = red[0];
    __syncthreads();

    // ===== blocked inversion: W = L^{-1} =====
    for (int t = tid; t < 16384; t += 256) P[t] = 0.f;
    __syncthreads();

    for (int rnd = 0; rnd < 2; ++rnd) {
        for (int e = tid; e < 1024; e += 256) {
            int ii = e >> 4, t4 = (e & 15) * 4;
            int K0 = 2 * rnd, K1 = 2 * rnd + 1;
            *(float4*)&As[ii * 64 + t4] =
                *(const float4*)&Mw[(64 * K0 + ii) * D_ + 64 * K0 + t4];
            *(float4*)&Bs[ii * 64 + t4] =
                *(const float4*)&Mw[(64 * K1 + ii) * D_ + 64 * K1 + t4];
        }
        __syncthreads();
        if (tid < 128) {
            const int g = tid >> 6;
            const int jj = tid & 63;
            const int K = 2 * rnd + g;
            float* WK = P + K * 4096;
            const float* Ld = g ? Bs : As;
            for (int ii = jj; ii < 64; ++ii) {
                float acc = (ii == jj) ? 1.f : 0.f;
                for (int t = jj; t < ii; ++t) acc -= Ld[ii * 64 + t] * WK[t * 64 + jj];
                WK[ii * 64 + jj] = acc / Ld[ii * 64 + ii];
            }
        }
        __syncthreads();
    }

    for (int e = tid; e < 8192; e += 256) {
        int Kb = e >> 11, rr = (e >> 5) & 63, c2 = (e & 31) * 2;
        float v0 = P[Kb * 4096 + rr * 64 + c2];
        float v1 = P[Kb * 4096 + rr * 64 + c2 + 1];
        int gi = (64 * Kb + rr) * D_ + 64 * Kb + c2;
        Wg[gi] = v0; Wg[gi + 1] = v1;
        uint32_t lo, hi = pack_split(v0, v1, lo);
        *(uint32_t*)&g_bfH[sb + gi] = hi;
        *(uint32_t*)&g_bfL[sb + gi] = lo;
    }
    for (int e = tid; e < 6 * 2048; e += 256) {
        int bb = e >> 11, rr = (e >> 5) & 63, c2 = (e & 31) * 2;
        int I = (bb < 3) ? 0 : ((bb < 5) ? 1 : 2);
        int J = (bb < 3) ? (bb + 1) : ((bb == 3) ? 2 : 3);
        int gi = (64 * I + rr) * D_ + 64 * J + c2;
        Wg[gi] = 0.f; Wg[gi + 1] = 0.f;
        *(uint32_t*)&g_bfH[sb + gi] = 0u;
        *(uint32_t*)&g_bfL[sb + gi] = 0u;
    }
    __syncthreads();

    for (int J = 0; J < 3; ++J) {
        for (int I = J + 1; I < 4; ++I) {
            float acc[4][4];
#pragma unroll
            for (int r = 0; r < 4; ++r)
#pragma unroll
                for (int c = 0; c < 4; ++c) acc[r][c] = 0.f;

            for (int K = J; K < I; ++K) {
                __syncthreads();
                for (int e = tid; e < 1024; e += 256) {
                    int k = e >> 4, r4 = (e & 15) * 4;
                    float4 v = *(const float4*)&LT[(64 * K + k) * D_ + 64 * I + r4];
                    *(float4*)&As[k * PPAD + r4] = v;
                }
                for (int e = tid; e < 1024; e += 256) {
                    int k = e >> 4, c4 = (e & 15) * 4;
                    float4 v;
                    if (K == J) {
                        v = make_float4(P[J * 4096 + k * 64 + c4 + 0],
                                        P[J * 4096 + k * 64 + c4 + 1],
                                        P[J * 4096 + k * 64 + c4 + 2],
                                        P[J * 4096 + k * 64 + c4 + 3]);
                    } else {
                        v = *(const float4*)&Wg[(64 * K + k) * D_ + 64 * J + c4];
                    }
                    *(float4*)&Bs[k * PPAD + c4] = v;
                }
                __syncthreads();
#pragma unroll 4
                for (int kk = 0; kk < 64; ++kk) {
                    float4 a = *(const float4*)&As[kk * PPAD + rg];
                    float4 b = *(const float4*)&Bs[kk * PPAD + cg];
                    float av[4] = {a.x, a.y, a.z, a.w};
                    float bv[4] = {b.x, b.y, b.z, b.w};
#pragma unroll
                    for (int r = 0; r < 4; ++r)
#pragma unroll
                        for (int c = 0; c < 4; ++c) acc[r][c] += av[r] * bv[c];
                }
            }
            __syncthreads();
#pragma unroll
            for (int r = 0; r < 4; ++r)
#pragma unroll
                for (int c = 0; c < 4; ++c)
                    Bs[(rg + r) * PPAD + cg + c] = acc[r][c];
            __syncthreads();
            float o[4][4];
#pragma unroll
            for (int r = 0; r < 4; ++r)
#pragma unroll
                for (int c = 0; c < 4; ++c) o[r][c] = 0.f;
            const float* wA = P + I * 4096;
#pragma unroll 4
            for (int kk = 0; kk < 64; ++kk) {
                float av[4];
#pragma unroll
                for (int r = 0; r < 4; ++r) av[r] = wA[(rg + r) * 64 + kk];
                float4 b = *(const float4*)&Bs[kk * PPAD + cg];
                float bv[4] = {b.x, b.y, b.z, b.w};
#pragma unroll
                for (int r = 0; r < 4; ++r)
#pragma unroll
                    for (int c = 0; c < 4; ++c) o[r][c] += av[r] * bv[c];
            }
#pragma unroll
            for (int r = 0; r < 4; ++r) {
                float n0 = -o[r][0], n1 = -o[r][1], n2 = -o[r][2], n3 = -o[r][3];
                int gi = (64 * I + rg + r) * D_ + 64 * J + cg;
                *(float4*)&Wg[gi] = make_float4(n0, n1, n2, n3);
                uint32_t l01, l23;
                uint32_t h01 = pack_split(n0, n1, l01);
                uint32_t h23 = pack_split(n2, n3, l23);
                *(uint2*)&g_bfH[sb + gi] = make_uint2(h01, h23);
                *(uint2*)&g_bfL[sb + gi] = make_uint2(l01, l23);
            }
        }
    }
}

// ---------------------------------------------------------------------------
// Kernel 3: maha via mma.sync bf16 split GEMM + square-reduce epilogue.
// (identical to R16: 2 CTAs/SM, a-frags loaded per-mt)
// ---------------------------------------------------------------------------
#define MAHA_SMEM (4 * ABUF * 2 + 256 * 4)

__global__ __launch_bounds__(256, 2) void maha_mma_kernel(const float* __restrict__ x,
                                                          const float* __restrict__ mu,
                                                          float* __restrict__ out) {
    extern __shared__ char shm[];
    __nv_bfloat16* AH = (__nv_bfloat16*)shm;
    __nv_bfloat16* AL = AH + ABUF;
    __nv_bfloat16* BH = AL + ABUF;
    __nv_bfloat16* BL = BH + ABUF;
    float* sacc = (float*)(shm + 4 * ABUF * 2);   // [2 warp-rows][128 cols]

    const int s = blockIdx.y;
    const int b0 = blockIdx.x * 128;
    const int tid = threadIdx.x;
    const int wid = tid >> 5, lane = tid & 31;
    const int wr = wid >> 2;
    const int wc = wid & 3;

    sacc[tid] = 0.f;
    __syncthreads();

    const int sb = s * 65536;
    const int srow = tid >> 3;              // 0..31 (B staging row group)
    const int sk8  = (tid & 7) * 8;
    const int rowq = tid >> 1, half = tid & 1;   // A staging

    for (int dt = 0; dt < 2; ++dt) {
        float c[4][4][4];
#pragma unroll
        for (int mt = 0; mt < 4; ++mt)
#pragma unroll
            for (int nt = 0; nt < 4; ++nt)
#pragma unroll
                for (int q = 0; q < 4; ++q) c[mt][nt][q] = 0.f;

        const int nch = dt ? 4 : 2;          // d-tile 0: W zero beyond k=128
        for (int ch = 0; ch < nch; ++ch) {
            const int k0 = ch * 64;
            __syncthreads();
            // ---- stage A: direct bf16 copies from g_bfH/g_bfL ----
#pragma unroll
            for (int j = 0; j < 4; ++j) {
                int kc = half * 32 + j * 8;
                int ga = sb + (dt * 128 + rowq) * 256 + k0 + kc;
                *(uint4*)(AH + rowq * ASTRIDE + kc) = *(const uint4*)&g_bfH[ga];
                *(uint4*)(AL + rowq * ASTRIDE + kc) = *(const uint4*)&g_bfL[ga];
            }
            // ---- stage B = x[b0+row] - mu[s], split on the fly ----
#pragma unroll
            for (int it = 0; it < 4; ++it) {
                int row = srow + it * 32;
                const float* px = x + (b0 + row) * 256 + k0 + sk8;
                const float* pm = mu + s * 256 + k0 + sk8;
                float4 u = *(const float4*)px;
                float4 um = *(const float4*)pm;
                float4 v = *(const float4*)(px + 4);
                float4 vm = *(const float4*)(pm + 4);
                u.x -= um.x; u.y -= um.y; u.z -= um.z; u.w -= um.w;
                v.x -= vm.x; v.y -= vm.y; v.z -= vm.z; v.w -= vm.w;
                uint4 hq, lq; split8(u, v, hq, lq);
                *(uint4*)(BH + row * ASTRIDE + sk8) = hq;
                *(uint4*)(BL + row * ASTRIDE + sk8) = lq;
            }
            __syncthreads();

            const int ar = lane & 15, as8 = (lane >> 4) * 8;
            const int br = lane & 7,  bs8 = ((lane >> 3) & 1) * 8;
#pragma unroll
            for (int ks = 0; ks < 4; ++ks) {
                const int kk = ks * 16;
                uint32_t bH[4][2], bL[4][2];
#pragma unroll
                for (int nt = 0; nt < 4; ++nt) {
                    int row = wc * 32 + nt * 8 + br;
                    LDSM_X2(bH[nt], smem_u32(BH + row * ASTRIDE + kk + bs8));
                    LDSM_X2(bL[nt], smem_u32(BL + row * ASTRIDE + kk + bs8));
                }
#pragma unroll
                for (int mt = 0; mt < 4; ++mt) {
                    int row = wr * 64 + mt * 16 + ar;
                    uint32_t aH[4], aL[4];
                    LDSM_X4(aH, smem_u32(AH + row * ASTRIDE + kk + as8));
                    LDSM_X4(aL, smem_u32(AL + row * ASTRIDE + kk + as8));
#pragma unroll
                    for (int nt = 0; nt < 4; ++nt) {
                        MMA16816(c[mt][nt], aH, bH[nt]);
                        MMA16816(c[mt][nt], aH, bL[nt]);
                        MMA16816(c[mt][nt], aL, bH[nt]);
                    }
                }
            }
        }

        // ---- epilogue: square + reduce over d within warp, slot-accumulate ----
#pragma unroll
        for (int nt = 0; nt < 4; ++nt) {
            float p0 = 0.f, p1 = 0.f;
#pragma unroll
            for (int mt = 0; mt < 4; ++mt) {
                p0 += c[mt][nt][0] * c[mt][nt][0] + c[mt][nt][2] * c[mt][nt][2];
                p1 += c[mt][nt][1] * c[mt][nt][1] + c[mt][nt][3] * c[mt][nt][3];
            }
#pragma unroll
            for (int m = 4; m <= 16; m <<= 1) {
                p0 += __shfl_xor_sync(0xffffffffu, p0, m);
                p1 += __shfl_xor_sync(0xffffffffu, p1, m);
            }
            if (lane < 4) {
                int col = wc * 32 + nt * 8 + 2 * lane;
                sacc[wr * 128 + col]     += p0;
                sacc[wr * 128 + col + 1] += p1;
            }
        }
    }

    __syncthreads();
    if (tid < 128) {
        float m = sacc[tid] + sacc[128 + tid];
        out[(b0 + tid) * S_ + s] = -0.5f * ((float)D_ * LOG2PI + g_logdet[s] + m);
    }
}

// ---------------------------------------------------------------------------
extern "C" void kernel_launch(void* const* d_in, const int* in_sizes, int n_in,
                              void* d_out, int out_size) {
    const float* x  = (const float*)d_in[0];   // (B, D)
    const float* mu = (const float*)d_in[1];   // (S, 1, D)
    const float* sp = (const float*)d_in[2];   // (S, 1, D, D)
    float* out = (float*)d_out;                // (B, S)

    const int chol_smem = CHOL_SMEM_FLOATS * sizeof(float);   // 107,520 B
    cudaFuncSetAttribute(cholinv_kernel,
                         cudaFuncAttributeMaxDynamicSharedMemorySize, chol_smem);
    cudaFuncSetAttribute(gram_mma_kernel,
                         cudaFuncAttributeMaxDynamicSharedMemorySize, GEMM_SMEM);
    cudaFuncSetAttribute(maha_mma_kernel,
                         cudaFuncAttributeMaxDynamicSharedMemorySize, MAHA_SMEM);

    tsplit_kernel<<<dim3(16, S_), 256>>>(sp);
    gram_mma_kernel<<<dim3(3, S_), 256, GEMM_SMEM>>>();
    cholinv_kernel<<<S_, 256, chol_smem>>>();
    maha_mma_kernel<<<dim3(B_ / 128, S_), 256, MAHA_SMEM>>>(x, mu, out);
}